// round 1
// baseline (speedup 1.0000x reference)
#include <cuda_runtime.h>
#include <cstdint>

#define BATCH     64
#define HH        1024
#define WW        1024
#define OUTN      256
#define ROWS_PER_BLOCK 32
#define BLOCKS_PER_BATCH (HH / ROWS_PER_BLOCK)   // 32
#define QUADS_PER_ROW (WW / 4)                   // 256

// Exact-integer per-batch statistics scratch (device globals: no allocs allowed).
__device__ int g_area[BATCH];
__device__ int g_sumr[BATCH];
__device__ int g_sumc[BATCH];
__device__ int g_minr[BATCH];
__device__ int g_maxr[BATCH];
__device__ int g_minc[BATCH];
__device__ int g_maxc[BATCH];

__global__ void gss_init_kernel() {
    int b = threadIdx.x;
    if (b < BATCH) {
        g_area[b] = 0;
        g_sumr[b] = 0;
        g_sumc[b] = 0;
        g_minr[b] = HH;
        g_maxr[b] = -1;
        g_minc[b] = WW;
        g_maxc[b] = -1;
    }
}

__global__ __launch_bounds__(256) void gss_reduce_kernel(const float4* __restrict__ mask) {
    const int blk   = blockIdx.x;
    const int batch = blk / BLOCKS_PER_BATCH;
    const int row0  = (blk % BLOCKS_PER_BATCH) * ROWS_PER_BLOCK;
    const int t     = threadIdx.x;            // 0..255, one float4 column-quad per thread
    const int col0  = t * 4;

    const float4* base = mask
        + (size_t)batch * (HH * QUADS_PER_ROW)
        + (size_t)row0 * QUADS_PER_ROW
        + t;

    int count = 0, sumr = 0, sumc = 0;
    int minr = HH, maxr = -1, minc = WW, maxc = -1;

    #pragma unroll 4
    for (int r = 0; r < ROWS_PER_BLOCK; ++r) {
        float4 v = __ldcs(base + (size_t)r * QUADS_PER_ROW);  // streaming: no reuse
        int i0 = (v.x != 0.0f);
        int i1 = (v.y != 0.0f);
        int i2 = (v.z != 0.0f);
        int i3 = (v.w != 0.0f);
        int rc = i0 + i1 + i2 + i3;
        if (rc) {
            int row = row0 + r;
            count += rc;
            sumr  += row * rc;
            sumc  += col0 * rc + i1 + 2 * i2 + 3 * i3;
            minr = min(minr, row);
            maxr = row;  // rows ascend within the loop
            unsigned m = (unsigned)(i0 | (i1 << 1) | (i2 << 2) | (i3 << 3));
            minc = min(minc, col0 + (__ffs(m) - 1));
            maxc = max(maxc, col0 + (31 - __clz(m)));
        }
    }

    // Warp-level reduction
    const unsigned full = 0xFFFFFFFFu;
    #pragma unroll
    for (int off = 16; off > 0; off >>= 1) {
        count += __shfl_down_sync(full, count, off);
        sumr  += __shfl_down_sync(full, sumr,  off);
        sumc  += __shfl_down_sync(full, sumc,  off);
        minr  = min(minr, __shfl_down_sync(full, minr, off));
        maxr  = max(maxr, __shfl_down_sync(full, maxr, off));
        minc  = min(minc, __shfl_down_sync(full, minc, off));
        maxc  = max(maxc, __shfl_down_sync(full, maxc, off));
    }

    __shared__ int s_cnt[8], s_sr[8], s_sc[8], s_mnr[8], s_mxr[8], s_mnc[8], s_mxc[8];
    int wid = t >> 5, lid = t & 31;
    if (lid == 0) {
        s_cnt[wid] = count; s_sr[wid] = sumr; s_sc[wid] = sumc;
        s_mnr[wid] = minr;  s_mxr[wid] = maxr;
        s_mnc[wid] = minc;  s_mxc[wid] = maxc;
    }
    __syncthreads();

    if (wid == 0 && lid < 8) {
        count = s_cnt[lid]; sumr = s_sr[lid]; sumc = s_sc[lid];
        minr = s_mnr[lid]; maxr = s_mxr[lid];
        minc = s_mnc[lid]; maxc = s_mxc[lid];
        #pragma unroll
        for (int off = 4; off > 0; off >>= 1) {
            count += __shfl_down_sync(0xFF, count, off);
            sumr  += __shfl_down_sync(0xFF, sumr,  off);
            sumc  += __shfl_down_sync(0xFF, sumc,  off);
            minr  = min(minr, __shfl_down_sync(0xFF, minr, off));
            maxr  = max(maxr, __shfl_down_sync(0xFF, maxr, off));
            minc  = min(minc, __shfl_down_sync(0xFF, minc, off));
            maxc  = max(maxc, __shfl_down_sync(0xFF, maxc, off));
        }
        if (lid == 0) {
            if (count > 0) {
                atomicAdd(&g_area[batch], count);
                atomicAdd(&g_sumr[batch], sumr);
                atomicAdd(&g_sumc[batch], sumc);
                atomicMin(&g_minr[batch], minr);
                atomicMax(&g_maxr[batch], maxr);
                atomicMin(&g_minc[batch], minc);
                atomicMax(&g_maxc[batch], maxc);
            }
        }
    }
}

__global__ __launch_bounds__(OUTN) void gss_finalize_kernel(const float* __restrict__ Wm,
                                                            const float* __restrict__ bias,
                                                            float* __restrict__ out) {
    int b = blockIdx.x;
    int o = threadIdx.x;

    float f0 = 0.f, f1 = 0.f, f2 = 0.f, f3 = 0.f, f4 = 0.f, f5 = 0.f;
    int area = g_area[b];
    if (area > 0) {
        float fa = (float)area;
        float cr = (float)g_sumr[b] / fa;
        float cc = (float)g_sumc[b] / fa;
        float height = (float)(g_maxr[b] - g_minr[b]);
        float width  = (float)(g_maxc[b] - g_minc[b]);
        const float hw = (float)HH * (float)WW;
        f0 = cr / (float)HH;
        f1 = cc / (float)WW;
        f2 = height / (float)HH;
        f3 = width / (float)WW;
        f4 = fa / hw;
        f5 = height * width / hw;
    }

    const float* wrow = Wm + o * 6;
    float acc = bias[o];
    acc = fmaf(f0, wrow[0], acc);
    acc = fmaf(f1, wrow[1], acc);
    acc = fmaf(f2, wrow[2], acc);
    acc = fmaf(f3, wrow[3], acc);
    acc = fmaf(f4, wrow[4], acc);
    acc = fmaf(f5, wrow[5], acc);
    out[b * OUTN + o] = acc;
}

extern "C" void kernel_launch(void* const* d_in, const int* in_sizes, int n_in,
                              void* d_out, int out_size) {
    const float* mask = (const float*)d_in[0];   // (64,1,1024,1024) fp32
    const float* Wm   = (const float*)d_in[1];   // (256,6) fp32
    const float* bias = (const float*)d_in[2];   // (256,) fp32
    float* out = (float*)d_out;                  // (64,256) fp32

    gss_init_kernel<<<1, BATCH>>>();
    gss_reduce_kernel<<<BATCH * BLOCKS_PER_BATCH, 256>>>((const float4*)mask);
    gss_finalize_kernel<<<BATCH, OUTN>>>(Wm, bias, out);
}